// round 9
// baseline (speedup 1.0000x reference)
#include <cuda_runtime.h>
#include <cstdint>

// QPChargeNormalization — persistent, register double-buffered software
// pipeline. Loads for row j+1 are issued before row j is consumed, so the
// DRAM request stream never pauses during the reduce/store phase.
//
// Per row b (B=4096): n=8192, c=[c_iso|c_aniso], q=[int_iso|int_aniso]
//   h = (sum(charge[b]) - q.c) / (q.q),  x = c + h*q
// Output = [sol_iso (B*4096) | sol_aniso (B*4096)]

#define NT    512
#define GRID  148          // 1 persistent CTA per SM
#define NCH   256

struct RowData {
    float4 c0, c1, c2, c3;
    float4 q0, q1, q2, q3;
    float  Qv;
};

__device__ __forceinline__ float dot4(float4 a, float4 b) {
    return fmaf(a.x, b.x, fmaf(a.y, b.y, fmaf(a.z, b.z, a.w * b.w)));
}

__device__ __forceinline__ float4 axpy4(float h, float4 q, float4 c) {
    float4 o;
    o.x = fmaf(h, q.x, c.x);
    o.y = fmaf(h, q.y, c.y);
    o.z = fmaf(h, q.z, c.z);
    o.w = fmaf(h, q.w, c.w);
    return o;
}

__device__ __forceinline__ void load_row(RowData& d,
                                         const float4* __restrict__ c_iso,
                                         const float4* __restrict__ c_aniso,
                                         const float4* __restrict__ q_iso,
                                         const float4* __restrict__ q_aniso,
                                         const float*  __restrict__ charge,
                                         int r, int tid)
{
    const size_t row4 = (size_t)r * 1024;
    d.c0 = c_iso  [row4 + tid];
    d.c1 = c_iso  [row4 + tid + NT];
    d.c2 = c_aniso[row4 + tid];
    d.c3 = c_aniso[row4 + tid + NT];
    d.q0 = q_iso  [row4 + tid];
    d.q1 = q_iso  [row4 + tid + NT];
    d.q2 = q_aniso[row4 + tid];
    d.q3 = q_aniso[row4 + tid + NT];
    d.Qv = (tid < NCH) ? charge[(size_t)r * NCH + tid] : 0.0f;
}

__device__ __forceinline__ void process_row(const RowData& d,
                                            float4* __restrict__ out,
                                            float* s_p, int r, int B,
                                            int tid, int wid, int lane)
{
    float qc = dot4(d.q0, d.c0) + dot4(d.q1, d.c1)
             + dot4(d.q2, d.c2) + dot4(d.q3, d.c3);
    float qq = dot4(d.q0, d.q0) + dot4(d.q1, d.q1)
             + dot4(d.q2, d.q2) + dot4(d.q3, d.q3);
    float Qv = d.Qv;

    #pragma unroll
    for (int m = 16; m; m >>= 1) {
        qc += __shfl_xor_sync(0xffffffffu, qc, m);
        qq += __shfl_xor_sync(0xffffffffu, qq, m);
        Qv += __shfl_xor_sync(0xffffffffu, Qv, m);
    }
    if (lane == 0) { s_p[wid] = qc; s_p[16 + wid] = qq; s_p[32 + wid] = Qv; }
    __syncthreads();

    // Every warp redundantly reduces the 16 partials (no broadcast needed).
    float sa = (lane < 16) ? s_p[lane]      : 0.0f;
    float sg = (lane < 16) ? s_p[16 + lane] : 0.0f;
    float sq = (lane < 16) ? s_p[32 + lane] : 0.0f;
    #pragma unroll
    for (int m = 8; m; m >>= 1) {
        sa += __shfl_xor_sync(0xffffffffu, sa, m);
        sg += __shfl_xor_sync(0xffffffffu, sg, m);
        sq += __shfl_xor_sync(0xffffffffu, sq, m);
    }
    const float h = __shfl_sync(0xffffffffu, (sq - sa) / sg, 0);
    __syncthreads();   // safe s_p reuse next row; cost hidden by in-flight loads

    const size_t row4 = (size_t)r * 1024;
    float4* oi = out + row4;                        // iso block
    float4* oa = out + (size_t)B * 1024 + row4;     // aniso block
    oi[tid]      = axpy4(h, d.q0, d.c0);
    oi[tid + NT] = axpy4(h, d.q1, d.c1);
    oa[tid]      = axpy4(h, d.q2, d.c2);
    oa[tid + NT] = axpy4(h, d.q3, d.c3);
}

__global__ void __launch_bounds__(NT, 1)
qp_pipe_kernel(const float4* __restrict__ c_iso,
               const float4* __restrict__ c_aniso,
               const float4* __restrict__ q_iso,
               const float4* __restrict__ q_aniso,
               const float*  __restrict__ charge,
               float4*       __restrict__ out,
               int B)
{
    const int tid  = threadIdx.x;
    const int wid  = tid >> 5;
    const int lane = tid & 31;

    __shared__ float s_p[48];

    int r = blockIdx.x;
    if (r >= B) return;

    RowData A, Bf;
    load_row(A, c_iso, c_aniso, q_iso, q_aniso, charge, r, tid);

    for (;;) {
        // Issue next row's loads BEFORE consuming the current row, so the
        // DRAM stream stays busy through the reduce/store phase below.
        int rn = r + GRID;
        bool nextA = (rn < B);
        if (nextA)
            load_row(Bf, c_iso, c_aniso, q_iso, q_aniso, charge, rn, tid);

        process_row(A, out, s_p, r, B, tid, wid, lane);
        if (!nextA) return;
        r = rn;

        rn = r + GRID;
        bool nextB = (rn < B);
        if (nextB)
            load_row(A, c_iso, c_aniso, q_iso, q_aniso, charge, rn, tid);

        process_row(Bf, out, s_p, r, B, tid, wid, lane);
        if (!nextB) return;
        r = rn;
    }
}

extern "C" void kernel_launch(void* const* d_in, const int* in_sizes, int n_in,
                              void* d_out, int out_size)
{
    const float4* c_iso   = (const float4*)d_in[0];
    const float4* c_aniso = (const float4*)d_in[1];
    const float4* q_iso   = (const float4*)d_in[2];
    const float4* q_aniso = (const float4*)d_in[3];
    const float*  charge  = (const float*) d_in[4];
    float4*       out     = (float4*)d_out;

    const int B = in_sizes[4] / NCH;   // charge is [B, 256]

    qp_pipe_kernel<<<GRID, NT>>>(c_iso, c_aniso, q_iso, q_aniso,
                                 charge, out, B);
}